// round 2
// baseline (speedup 1.0000x reference)
#include <cuda_runtime.h>
#include <cuda_bf16.h>
#include <cstdint>

// Problem constants (fixed by the dataset)
#define BB 4
#define N1 2048
#define N2 2048
#define FF 256
#define NEG_ALPHA 0.2f

// Scratch (static __device__ — no allocations allowed)
__device__ float g_v1[FF];
__device__ float g_v2[FF];
__device__ float g_s1[BB * N2];   // word · v1  (per column j)
__device__ float g_t2[BB * N2];   // word · v2
__device__ float g_e1[BB * N2];   // exp(s1)
__device__ float g_p1[BB * N2];   // exp(0.2*s1)
__device__ float g_w[(size_t)BB * N1 * N2];  // attention weights (tf32-rounded), 64MB

__device__ __forceinline__ uint32_t f2tf32(float x) {
    uint32_t u;
    asm("cvt.rna.tf32.f32 %0, %1;" : "=r"(u) : "f"(x));
    return u;
}

// ---------------------------------------------------------------------------
// K1: v1 = W1 @ w3[:256], v2 = W2 @ w3[256:]   (one warp per output element)
// ---------------------------------------------------------------------------
__global__ void k1_vec(const float* __restrict__ W1, const float* __restrict__ W2,
                       const float* __restrict__ w3) {
    int gw   = blockIdx.x * 8 + (threadIdx.x >> 5);  // 0..511
    int lane = threadIdx.x & 31;
    int which = gw >> 8;          // 0 -> v1, 1 -> v2
    int f     = gw & 255;
    const float* W = which ? W2 : W1;
    const float* w = w3 + (which ? FF : 0);
    float s = 0.f;
    #pragma unroll
    for (int k = 0; k < 8; k++)
        s += W[f * FF + lane + 32 * k] * w[lane + 32 * k];
    #pragma unroll
    for (int o = 16; o > 0; o >>= 1)
        s += __shfl_down_sync(0xffffffffu, s, o);
    if (lane == 0) {
        if (which) g_v2[f] = s; else g_v1[f] = s;
    }
}

// ---------------------------------------------------------------------------
// K2: per node j: s1 = word_j·v1, t2 = word_j·v2, e1 = exp(s1), p1 = exp(.2 s1)
// ---------------------------------------------------------------------------
__global__ void k2_proj(const float* __restrict__ word) {
    int row  = blockIdx.x * 8 + (threadIdx.x >> 5);
    int lane = threadIdx.x & 31;
    const float* wr = word + (size_t)row * FF;
    float s = 0.f, t = 0.f;
    #pragma unroll
    for (int k = 0; k < 8; k++) {
        float x = wr[lane + 32 * k];
        s += x * g_v1[lane + 32 * k];
        t += x * g_v2[lane + 32 * k];
    }
    #pragma unroll
    for (int o = 16; o > 0; o >>= 1) {
        s += __shfl_down_sync(0xffffffffu, s, o);
        t += __shfl_down_sync(0xffffffffu, t, o);
    }
    if (lane == 0) {
        g_s1[row] = s;
        g_t2[row] = t;
        g_e1[row] = __expf(s);
        g_p1[row] = __expf(NEG_ALPHA * s);
    }
}

// ---------------------------------------------------------------------------
// K3: per output row (b,i): deg, s2 = (Σ adj·t2)/max(deg,1),
//     Z = Σ adj·exp(exp(lrelu(s2+s1_j))), then write the full softmax weight
//     row into g_w (tf32-rounded).  One 256-thread block per row.
// ---------------------------------------------------------------------------
__global__ void k3_stats(const float* __restrict__ adj) {
    __shared__ float shd[8], shs[8];
    __shared__ float bc[4];
    int row = blockIdx.x;
    int b   = row >> 11;
    int tid = threadIdx.x;
    const float* ar = adj + (size_t)row * N2;
    int base = b << 11;

    float a[8];
    float deg = 0.f, sr = 0.f;
    #pragma unroll
    for (int k = 0; k < 8; k++) {
        a[k] = ar[tid + 256 * k];
        deg += a[k];
        sr  += a[k] * g_t2[base + tid + 256 * k];
    }
    #pragma unroll
    for (int o = 16; o > 0; o >>= 1) {
        deg += __shfl_down_sync(0xffffffffu, deg, o);
        sr  += __shfl_down_sync(0xffffffffu, sr,  o);
    }
    int w = tid >> 5, ln = tid & 31;
    if (ln == 0) { shd[w] = deg; shs[w] = sr; }
    __syncthreads();
    if (tid == 0) {
        float D = 0.f, S = 0.f;
        #pragma unroll
        for (int q = 0; q < 8; q++) { D += shd[q]; S += shs[q]; }
        float s2 = S / fmaxf(D, 1.0f);
        bc[0] = s2;
        bc[1] = __expf(s2);
        bc[2] = __expf(NEG_ALPHA * s2);
        bc[3] = D;
    }
    __syncthreads();
    float s2 = bc[0], E2 = bc[1], P2 = bc[2], D = bc[3];

    // e_ij = exp(exp(lrelu(s2+s1_j))); lrelu factorized through precomputed exps
    float e[8];
    float z = 0.f;
    #pragma unroll
    for (int k = 0; k < 8; k++) {
        int j = base + tid + 256 * k;
        float pre   = s2 + g_s1[j];
        float inner = (pre >= 0.f) ? E2 * g_e1[j] : P2 * g_p1[j];
        e[k] = __expf(inner);
        z   += a[k] * e[k];
    }
    #pragma unroll
    for (int o = 16; o > 0; o >>= 1) z += __shfl_down_sync(0xffffffffu, z, o);
    if (ln == 0) shd[w] = z;
    __syncthreads();
    if (tid == 0) {
        float Z = 0.f;
        #pragma unroll
        for (int q = 0; q < 8; q++) Z += shd[q];
        bc[0] = (D > 0.f) ? (1.0f / Z) : -1.0f;
    }
    __syncthreads();
    float invZ = bc[0];

    float* wr = g_w + (size_t)row * N2;
    #pragma unroll
    for (int k = 0; k < 8; k++) {
        float wv = (invZ < 0.f) ? (1.0f / 2048.0f)
                                : (a[k] > 0.f ? e[k] * invZ : 0.f);
        wr[tid + 256 * k] = __uint_as_float(f2tf32(wv));
    }
}

// ---------------------------------------------------------------------------
// K4: edge = W @ word   (pure tf32 GEMM, A already tf32-rounded in g_w)
//     BM=64 BN=256 BK=32, 256 threads (8 warps in 2x4), register prefetch.
// ---------------------------------------------------------------------------
#define BM 64
#define BN 256
#define BK 32
#define AST 36   // A smem stride: bank = 4g+tg, all 32 distinct
#define BST 264  // B smem stride: 264%32=8 -> bank = 8tg+g, all 32 distinct

__device__ __forceinline__ void mma_tf32(float c[4], const uint32_t a[4],
                                         uint32_t b0, uint32_t b1) {
    asm volatile(
        "mma.sync.aligned.m16n8k8.row.col.f32.tf32.tf32.f32 "
        "{%0,%1,%2,%3},{%4,%5,%6,%7},{%8,%9},{%0,%1,%2,%3};"
        : "+f"(c[0]), "+f"(c[1]), "+f"(c[2]), "+f"(c[3])
        : "r"(a[0]), "r"(a[1]), "r"(a[2]), "r"(a[3]), "r"(b0), "r"(b1));
}

__global__ __launch_bounds__(256)
void k4_gemm(const float* __restrict__ word, float* __restrict__ out) {
    __shared__ __align__(16) float As[BM * AST];
    __shared__ __align__(16) float Bs[BK * BST];

    int b   = blockIdx.z;
    int i0  = blockIdx.y * BM;
    int tid = threadIdx.x;
    int wid = tid >> 5, lane = tid & 31;
    int g = lane >> 2, tg = lane & 3;
    int wm = (wid & 1) * 32;    // warp row offset (2 rows of warps)
    int wn = (wid >> 1) * 64;   // warp col offset (4 cols of warps)

    float acc[2][8][4];
    #pragma unroll
    for (int t = 0; t < 2; t++)
        #pragma unroll
        for (int u = 0; u < 8; u++)
            #pragma unroll
            for (int q = 0; q < 4; q++) acc[t][u][q] = 0.f;

    // A fill: rows arr, arr+32 ; cols acc4*4..+3
    int arr = tid >> 3, acc4 = tid & 7;
    const float* aptr = g_w + ((size_t)(b * N1 + i0 + arr)) * N2 + acc4 * 4;
    // B fill: rows bj + 4*it ; cols bf*4..+3
    int bj = tid >> 6, bf = tid & 63;
    const float* bptr = word + ((size_t)(b * N2 + bj)) * FF + bf * 4;

    float4 ra[2], rb[8];
    // prefetch tile 0
    ra[0] = *(const float4*)(aptr);
    ra[1] = *(const float4*)(aptr + (size_t)32 * N2);
    #pragma unroll
    for (int it = 0; it < 8; it++)
        rb[it] = *(const float4*)(bptr + (size_t)(4 * it) * FF);

    for (int kt = 0; kt < N2 / BK; kt++) {
        // ---- store current tile to smem (B converted to tf32) ----
        *(float4*)(As + arr * AST + acc4 * 4)        = ra[0];
        *(float4*)(As + (arr + 32) * AST + acc4 * 4) = ra[1];
        #pragma unroll
        for (int it = 0; it < 8; it++) {
            float4 v = rb[it];
            v.x = __uint_as_float(f2tf32(v.x));
            v.y = __uint_as_float(f2tf32(v.y));
            v.z = __uint_as_float(f2tf32(v.z));
            v.w = __uint_as_float(f2tf32(v.w));
            *(float4*)(Bs + (bj + 4 * it) * BST + bf * 4) = v;
        }
        __syncthreads();

        // ---- prefetch next tile (overlaps with mma below) ----
        if (kt + 1 < N2 / BK) {
            int k0 = (kt + 1) * BK;
            ra[0] = *(const float4*)(aptr + k0);
            ra[1] = *(const float4*)(aptr + (size_t)32 * N2 + k0);
            #pragma unroll
            for (int it = 0; it < 8; it++)
                rb[it] = *(const float4*)(bptr + (size_t)(k0 + 4 * it) * FF);
        }

        // ---- mma sweep: 4 k-steps of 8 ----
        #pragma unroll
        for (int s = 0; s < 4; s++) {
            int ks = s * 8;
            uint32_t afr[2][4];
            #pragma unroll
            for (int t = 0; t < 2; t++) {
                int mb = wm + t * 16;
                afr[t][0] = __float_as_uint(As[(mb + g)     * AST + ks + tg]);
                afr[t][1] = __float_as_uint(As[(mb + g + 8) * AST + ks + tg]);
                afr[t][2] = __float_as_uint(As[(mb + g)     * AST + ks + tg + 4]);
                afr[t][3] = __float_as_uint(As[(mb + g + 8) * AST + ks + tg + 4]);
            }
            #pragma unroll
            for (int u = 0; u < 8; u++) {
                uint32_t b0 = __float_as_uint(Bs[(ks + tg)     * BST + wn + u * 8 + g]);
                uint32_t b1 = __float_as_uint(Bs[(ks + tg + 4) * BST + wn + u * 8 + g]);
                #pragma unroll
                for (int t = 0; t < 2; t++)
                    mma_tf32(acc[t][u], afr[t], b0, b1);
            }
        }
        __syncthreads();
    }

    // ---- epilogue: float2 stores ----
    #pragma unroll
    for (int t = 0; t < 2; t++) {
        int rowg = i0 + wm + t * 16 + g;
        #pragma unroll
        for (int u = 0; u < 8; u++) {
            int col = wn + u * 8 + 2 * tg;
            float2 v0 = make_float2(acc[t][u][0], acc[t][u][1]);
            float2 v1 = make_float2(acc[t][u][2], acc[t][u][3]);
            *(float2*)(out + ((size_t)(b * N1 + rowg)) * FF + col)     = v0;
            *(float2*)(out + ((size_t)(b * N1 + rowg + 8)) * FF + col) = v1;
        }
    }
}

// ---------------------------------------------------------------------------
extern "C" void kernel_launch(void* const* d_in, const int* in_sizes, int n_in,
                              void* d_out, int out_size) {
    (void)out_size;
    // Defensive input identification by element count.
    const float *word = nullptr, *adj = nullptr, *W1 = nullptr, *W2 = nullptr, *w3 = nullptr;
    for (int i = 0; i < n_in; i++) {
        int sz = in_sizes[i];
        const float* p = (const float*)d_in[i];
        if      (sz == BB * N1 * N2) adj = p;
        else if (sz == BB * N2 * FF) word = p;
        else if (sz == 2 * FF)       w3 = p;
        else if (sz == FF * FF)      { if (!W1) W1 = p; else W2 = p; }
    }
    float* out = (float*)d_out;

    k1_vec<<<64, 256>>>(W1, W2, w3);
    k2_proj<<<(BB * N2) / 8, 256>>>(word);
    k3_stats<<<BB * N1, 256>>>(adj);
    k4_gemm<<<dim3(1, N1 / BM, BB), 256>>>(word, out);
}

// round 3
// speedup vs baseline: 1.2554x; 1.2554x over previous
#include <cuda_runtime.h>
#include <cuda_bf16.h>
#include <cstdint>

// Problem constants (fixed by the dataset)
#define BB 4
#define N1 2048
#define N2 2048
#define FF 256
#define NEG_ALPHA 0.2f

// Scratch (static __device__ — no allocations allowed)
__device__ float g_v1[FF];
__device__ float g_v2[FF];
__device__ float g_s1[BB * N2];   // word · v1  (per column j)
__device__ float g_t2[BB * N2];   // word · v2
__device__ float g_e1[BB * N2];   // exp(s1)
__device__ float g_p1[BB * N2];   // exp(0.2*s1)
__device__ float g_w[(size_t)BB * N1 * N2];  // attention weights (tf32-rounded), 64MB

__device__ __forceinline__ uint32_t f2tf32(float x) {
    uint32_t u;
    asm("cvt.rna.tf32.f32 %0, %1;" : "=r"(u) : "f"(x));
    return u;
}

// ---------------------------------------------------------------------------
// K1: v1 = W1 @ w3[:256], v2 = W2 @ w3[256:]   (one warp per output element)
// ---------------------------------------------------------------------------
__global__ void k1_vec(const float* __restrict__ W1, const float* __restrict__ W2,
                       const float* __restrict__ w3) {
    int gw   = blockIdx.x * 8 + (threadIdx.x >> 5);  // 0..511
    int lane = threadIdx.x & 31;
    int which = gw >> 8;          // 0 -> v1, 1 -> v2
    int f     = gw & 255;
    const float* W = which ? W2 : W1;
    const float* w = w3 + (which ? FF : 0);
    float s = 0.f;
    #pragma unroll
    for (int k = 0; k < 8; k++)
        s += W[f * FF + lane + 32 * k] * w[lane + 32 * k];
    #pragma unroll
    for (int o = 16; o > 0; o >>= 1)
        s += __shfl_down_sync(0xffffffffu, s, o);
    if (lane == 0) {
        if (which) g_v2[f] = s; else g_v1[f] = s;
    }
}

// ---------------------------------------------------------------------------
// K2: per node j: s1 = word_j·v1, t2 = word_j·v2, e1 = exp(s1), p1 = exp(.2 s1)
// ---------------------------------------------------------------------------
__global__ void k2_proj(const float* __restrict__ word) {
    int row  = blockIdx.x * 8 + (threadIdx.x >> 5);
    int lane = threadIdx.x & 31;
    const float* wr = word + (size_t)row * FF;
    float s = 0.f, t = 0.f;
    #pragma unroll
    for (int k = 0; k < 8; k++) {
        float x = wr[lane + 32 * k];
        s += x * g_v1[lane + 32 * k];
        t += x * g_v2[lane + 32 * k];
    }
    #pragma unroll
    for (int o = 16; o > 0; o >>= 1) {
        s += __shfl_down_sync(0xffffffffu, s, o);
        t += __shfl_down_sync(0xffffffffu, t, o);
    }
    if (lane == 0) {
        g_s1[row] = s;
        g_t2[row] = t;
        g_e1[row] = __expf(s);
        g_p1[row] = __expf(NEG_ALPHA * s);
    }
}

// ---------------------------------------------------------------------------
// K3: per output row (b,i): deg, s2 = (Σ adj·t2)/max(deg,1),
//     Z = Σ adj·exp(exp(lrelu(s2+s1_j))), then write the full softmax weight
//     row into g_w (tf32-rounded).  One 256-thread block per row.
// ---------------------------------------------------------------------------
__global__ void k3_stats(const float* __restrict__ adj) {
    __shared__ float shd[8], shs[8];
    __shared__ float bc[4];
    int row = blockIdx.x;
    int b   = row >> 11;
    int tid = threadIdx.x;
    const float* ar = adj + (size_t)row * N2;
    int base = b << 11;

    float a[8];
    float deg = 0.f, sr = 0.f;
    #pragma unroll
    for (int k = 0; k < 8; k++) {
        a[k] = ar[tid + 256 * k];
        deg += a[k];
        sr  += a[k] * g_t2[base + tid + 256 * k];
    }
    #pragma unroll
    for (int o = 16; o > 0; o >>= 1) {
        deg += __shfl_down_sync(0xffffffffu, deg, o);
        sr  += __shfl_down_sync(0xffffffffu, sr,  o);
    }
    int w = tid >> 5, ln = tid & 31;
    if (ln == 0) { shd[w] = deg; shs[w] = sr; }
    __syncthreads();
    if (tid == 0) {
        float D = 0.f, S = 0.f;
        #pragma unroll
        for (int q = 0; q < 8; q++) { D += shd[q]; S += shs[q]; }
        float s2 = S / fmaxf(D, 1.0f);
        bc[0] = s2;
        bc[1] = __expf(s2);
        bc[2] = __expf(NEG_ALPHA * s2);
        bc[3] = D;
    }
    __syncthreads();
    float s2 = bc[0], E2 = bc[1], P2 = bc[2], D = bc[3];

    // e_ij = exp(exp(lrelu(s2+s1_j))); lrelu factorized through precomputed exps
    float e[8];
    float z = 0.f;
    #pragma unroll
    for (int k = 0; k < 8; k++) {
        int j = base + tid + 256 * k;
        float pre   = s2 + g_s1[j];
        float inner = (pre >= 0.f) ? E2 * g_e1[j] : P2 * g_p1[j];
        e[k] = __expf(inner);
        z   += a[k] * e[k];
    }
    #pragma unroll
    for (int o = 16; o > 0; o >>= 1) z += __shfl_down_sync(0xffffffffu, z, o);
    if (ln == 0) shd[w] = z;
    __syncthreads();
    if (tid == 0) {
        float Z = 0.f;
        #pragma unroll
        for (int q = 0; q < 8; q++) Z += shd[q];
        bc[0] = (D > 0.f) ? (1.0f / Z) : -1.0f;
    }
    __syncthreads();
    float invZ = bc[0];

    float* wr = g_w + (size_t)row * N2;
    #pragma unroll
    for (int k = 0; k < 8; k++) {
        float wv = (invZ < 0.f) ? (1.0f / 2048.0f)
                                : (a[k] > 0.f ? e[k] * invZ : 0.f);
        wr[tid + 256 * k] = __uint_as_float(f2tf32(wv));
    }
}

// ---------------------------------------------------------------------------
// K4: edge = W @ word   (pure tf32 GEMM, A already tf32-rounded in g_w)
//     BM=64 BN=128 BK=32, 256 threads (8 warps in 2x4), register prefetch,
//     2 CTAs/SM for cross-CTA latency hiding.
// ---------------------------------------------------------------------------
#define BM 64
#define BN 128
#define BK 32
#define AST 36   // A smem stride: bank = 4g+tg, all 32 distinct
#define BST 136  // B smem stride: 136%32=8 -> bank = 8tg+g, all 32 distinct

__device__ __forceinline__ void mma_tf32(float c[4], const uint32_t a[4],
                                         uint32_t b0, uint32_t b1) {
    asm volatile(
        "mma.sync.aligned.m16n8k8.row.col.f32.tf32.tf32.f32 "
        "{%0,%1,%2,%3},{%4,%5,%6,%7},{%8,%9},{%0,%1,%2,%3};"
        : "+f"(c[0]), "+f"(c[1]), "+f"(c[2]), "+f"(c[3])
        : "r"(a[0]), "r"(a[1]), "r"(a[2]), "r"(a[3]), "r"(b0), "r"(b1));
}

__global__ __launch_bounds__(256, 2)
void k4_gemm(const float* __restrict__ word, float* __restrict__ out) {
    __shared__ __align__(16) float As[BM * AST];
    __shared__ __align__(16) float Bs[BK * BST];

    int b   = blockIdx.z;
    int i0  = blockIdx.y * BM;
    int f0  = blockIdx.x * BN;
    int tid = threadIdx.x;
    int wid = tid >> 5, lane = tid & 31;
    int g = lane >> 2, tg = lane & 3;
    int wm = (wid & 1) * 32;    // warp row offset (2 rows of warps)
    int wn = (wid >> 1) * 32;   // warp col offset (4 cols of warps)

    float acc[2][4][4];
    #pragma unroll
    for (int t = 0; t < 2; t++)
        #pragma unroll
        for (int u = 0; u < 4; u++)
            #pragma unroll
            for (int q = 0; q < 4; q++) acc[t][u][q] = 0.f;

    // A fill: rows arr, arr+32 ; cols acc4*4..+3
    int arr = tid >> 3, acc4 = tid & 7;
    const float* aptr = g_w + ((size_t)(b * N1 + i0 + arr)) * N2 + acc4 * 4;
    // B fill: rows bj + 8*it ; cols bf*4..+3 (of the BN=128 slice at f0)
    int bj = tid >> 5, bf = tid & 31;
    const float* bptr = word + ((size_t)(b * N2 + bj)) * FF + f0 + bf * 4;

    float4 ra[2], rb[4];
    // prefetch tile 0
    ra[0] = *(const float4*)(aptr);
    ra[1] = *(const float4*)(aptr + (size_t)32 * N2);
    #pragma unroll
    for (int it = 0; it < 4; it++)
        rb[it] = *(const float4*)(bptr + (size_t)(8 * it) * FF);

    for (int kt = 0; kt < N2 / BK; kt++) {
        // ---- store current tile to smem (B converted to tf32) ----
        *(float4*)(As + arr * AST + acc4 * 4)        = ra[0];
        *(float4*)(As + (arr + 32) * AST + acc4 * 4) = ra[1];
        #pragma unroll
        for (int it = 0; it < 4; it++) {
            float4 v = rb[it];
            v.x = __uint_as_float(f2tf32(v.x));
            v.y = __uint_as_float(f2tf32(v.y));
            v.z = __uint_as_float(f2tf32(v.z));
            v.w = __uint_as_float(f2tf32(v.w));
            *(float4*)(Bs + (bj + 8 * it) * BST + bf * 4) = v;
        }
        __syncthreads();

        // ---- prefetch next tile (overlaps with mma below) ----
        if (kt + 1 < N2 / BK) {
            int k0 = (kt + 1) * BK;
            ra[0] = *(const float4*)(aptr + k0);
            ra[1] = *(const float4*)(aptr + (size_t)32 * N2 + k0);
            #pragma unroll
            for (int it = 0; it < 4; it++)
                rb[it] = *(const float4*)(bptr + (size_t)(k0 + 8 * it) * FF);
        }

        // ---- mma sweep: 4 k-steps of 8 ----
        #pragma unroll
        for (int s = 0; s < 4; s++) {
            int ks = s * 8;
            uint32_t afr[2][4];
            #pragma unroll
            for (int t = 0; t < 2; t++) {
                int mb = wm + t * 16;
                afr[t][0] = __float_as_uint(As[(mb + g)     * AST + ks + tg]);
                afr[t][1] = __float_as_uint(As[(mb + g + 8) * AST + ks + tg]);
                afr[t][2] = __float_as_uint(As[(mb + g)     * AST + ks + tg + 4]);
                afr[t][3] = __float_as_uint(As[(mb + g + 8) * AST + ks + tg + 4]);
            }
            #pragma unroll
            for (int u = 0; u < 4; u++) {
                uint32_t b0 = __float_as_uint(Bs[(ks + tg)     * BST + wn + u * 8 + g]);
                uint32_t b1 = __float_as_uint(Bs[(ks + tg + 4) * BST + wn + u * 8 + g]);
                #pragma unroll
                for (int t = 0; t < 2; t++)
                    mma_tf32(acc[t][u], afr[t], b0, b1);
            }
        }
        __syncthreads();
    }

    // ---- epilogue: float2 stores ----
    #pragma unroll
    for (int t = 0; t < 2; t++) {
        int rowg = i0 + wm + t * 16 + g;
        #pragma unroll
        for (int u = 0; u < 4; u++) {
            int col = f0 + wn + u * 8 + 2 * tg;
            float2 v0 = make_float2(acc[t][u][0], acc[t][u][1]);
            float2 v1 = make_float2(acc[t][u][2], acc[t][u][3]);
            *(float2*)(out + ((size_t)(b * N1 + rowg)) * FF + col)     = v0;
            *(float2*)(out + ((size_t)(b * N1 + rowg + 8)) * FF + col) = v1;
        }
    }
}

// ---------------------------------------------------------------------------
extern "C" void kernel_launch(void* const* d_in, const int* in_sizes, int n_in,
                              void* d_out, int out_size) {
    (void)out_size;
    // Defensive input identification by element count.
    const float *word = nullptr, *adj = nullptr, *W1 = nullptr, *W2 = nullptr, *w3 = nullptr;
    for (int i = 0; i < n_in; i++) {
        int sz = in_sizes[i];
        const float* p = (const float*)d_in[i];
        if      (sz == BB * N1 * N2) adj = p;
        else if (sz == BB * N2 * FF) word = p;
        else if (sz == 2 * FF)       w3 = p;
        else if (sz == FF * FF)      { if (!W1) W1 = p; else W2 = p; }
    }
    float* out = (float*)d_out;

    k1_vec<<<64, 256>>>(W1, W2, w3);
    k2_proj<<<(BB * N2) / 8, 256>>>(word);
    k3_stats<<<BB * N1, 256>>>(adj);
    k4_gemm<<<dim3(FF / BN, N1 / BM, BB), 256>>>(word, out);
}

// round 8
// speedup vs baseline: 1.5627x; 1.2447x over previous
#include <cuda_runtime.h>
#include <cuda_fp16.h>
#include <cstdint>

// Problem constants (fixed by the dataset)
#define BB 4
#define N1 2048
#define N2 2048
#define FF 256
#define NEG_ALPHA 0.2f

// Scratch (static __device__ — no allocations allowed)
__device__ float g_v1[FF];
__device__ float g_v2[FF];
__device__ float g_s1[BB * N2];
__device__ float g_t2[BB * N2];
__device__ float g_e1[BB * N2];
__device__ float g_p1[BB * N2];
__device__ __half g_wh[(size_t)BB * N1 * N2];   // attention weights (fp16), 32MB
__device__ __half g_wth[(size_t)BB * FF * N2];  // word transposed (fp16): [b][f][k], 4MB

// ---------------------------------------------------------------------------
// K1: v1 = W1 @ w3[:256], v2 = W2 @ w3[256:]
// ---------------------------------------------------------------------------
__global__ void k1_vec(const float* __restrict__ W1, const float* __restrict__ W2,
                       const float* __restrict__ w3) {
    int gw   = blockIdx.x * 8 + (threadIdx.x >> 5);
    int lane = threadIdx.x & 31;
    int which = gw >> 8;
    int f     = gw & 255;
    const float* W = which ? W2 : W1;
    const float* w = w3 + (which ? FF : 0);
    float s = 0.f;
    #pragma unroll
    for (int k = 0; k < 8; k++)
        s += W[f * FF + lane + 32 * k] * w[lane + 32 * k];
    #pragma unroll
    for (int o = 16; o > 0; o >>= 1)
        s += __shfl_down_sync(0xffffffffu, s, o);
    if (lane == 0) {
        if (which) g_v2[f] = s; else g_v1[f] = s;
    }
}

// ---------------------------------------------------------------------------
// K2: per node j: s1, t2, exp(s1), exp(.2 s1)
// ---------------------------------------------------------------------------
__global__ void k2_proj(const float* __restrict__ word) {
    int row  = blockIdx.x * 8 + (threadIdx.x >> 5);
    int lane = threadIdx.x & 31;
    const float* wr = word + (size_t)row * FF;
    float s = 0.f, t = 0.f;
    #pragma unroll
    for (int k = 0; k < 8; k++) {
        float x = wr[lane + 32 * k];
        s += x * g_v1[lane + 32 * k];
        t += x * g_v2[lane + 32 * k];
    }
    #pragma unroll
    for (int o = 16; o > 0; o >>= 1) {
        s += __shfl_down_sync(0xffffffffu, s, o);
        t += __shfl_down_sync(0xffffffffu, t, o);
    }
    if (lane == 0) {
        g_s1[row] = s;
        g_t2[row] = t;
        g_e1[row] = __expf(s);
        g_p1[row] = __expf(NEG_ALPHA * s);
    }
}

// ---------------------------------------------------------------------------
// K2T: g_wth[b][f][k] = half(word[b][k][f])  (tiled transpose)
// ---------------------------------------------------------------------------
__global__ void k2t_transpose(const float* __restrict__ word) {
    __shared__ float t[32][33];
    int b  = blockIdx.z;
    int k0 = blockIdx.x * 32;
    int f0 = blockIdx.y * 32;
    int r = threadIdx.x >> 5;     // 0..7
    int c = threadIdx.x & 31;
    #pragma unroll
    for (int it = 0; it < 4; it++) {
        int k = k0 + r + 8 * it;
        t[r + 8 * it][c] = word[((size_t)(b * N2 + k)) * FF + f0 + c];
    }
    __syncthreads();
    #pragma unroll
    for (int it = 0; it < 4; it++) {
        int f = f0 + r + 8 * it;
        g_wth[((size_t)(b * FF + f)) * N2 + k0 + c] = __float2half_rn(t[c][r + 8 * it]);
    }
}

// ---------------------------------------------------------------------------
// K3: per output row (b,i): deg, s2, Z, then write softmax weights (fp16)
// ---------------------------------------------------------------------------
__global__ void k3_stats(const float* __restrict__ adj) {
    __shared__ float shd[8], shs[8];
    __shared__ float bc[4];
    int row = blockIdx.x;
    int b   = row >> 11;
    int tid = threadIdx.x;
    const float* ar = adj + (size_t)row * N2;
    int base = b << 11;

    float a[8];
    float deg = 0.f, sr = 0.f;
    #pragma unroll
    for (int k = 0; k < 8; k++) {
        a[k] = ar[tid + 256 * k];
        deg += a[k];
        sr  += a[k] * g_t2[base + tid + 256 * k];
    }
    #pragma unroll
    for (int o = 16; o > 0; o >>= 1) {
        deg += __shfl_down_sync(0xffffffffu, deg, o);
        sr  += __shfl_down_sync(0xffffffffu, sr,  o);
    }
    int w = tid >> 5, ln = tid & 31;
    if (ln == 0) { shd[w] = deg; shs[w] = sr; }
    __syncthreads();
    if (tid == 0) {
        float D = 0.f, S = 0.f;
        #pragma unroll
        for (int q = 0; q < 8; q++) { D += shd[q]; S += shs[q]; }
        float s2 = S / fmaxf(D, 1.0f);
        bc[0] = s2;
        bc[1] = __expf(s2);
        bc[2] = __expf(NEG_ALPHA * s2);
        bc[3] = D;
    }
    __syncthreads();
    float s2 = bc[0], E2 = bc[1], P2 = bc[2], D = bc[3];

    float e[8];
    float z = 0.f;
    #pragma unroll
    for (int k = 0; k < 8; k++) {
        int j = base + tid + 256 * k;
        float pre   = s2 + g_s1[j];
        float inner = (pre >= 0.f) ? E2 * g_e1[j] : P2 * g_p1[j];
        e[k] = __expf(inner);
        z   += a[k] * e[k];
    }
    #pragma unroll
    for (int o = 16; o > 0; o >>= 1) z += __shfl_down_sync(0xffffffffu, z, o);
    if (ln == 0) shd[w] = z;
    __syncthreads();
    if (tid == 0) {
        float Z = 0.f;
        #pragma unroll
        for (int q = 0; q < 8; q++) Z += shd[q];
        bc[0] = (D > 0.f) ? (1.0f / Z) : -1.0f;
    }
    __syncthreads();
    float invZ = bc[0];

    __half* wr = g_wh + (size_t)row * N2;
    #pragma unroll
    for (int k = 0; k < 8; k++) {
        float wv = (invZ < 0.f) ? (1.0f / 2048.0f)
                                : (a[k] > 0.f ? e[k] * invZ : 0.f);
        wr[tid + 256 * k] = __float2half_rn(wv);
    }
}

// ---------------------------------------------------------------------------
// K4: edge = W @ word^T' via HMMA mma.sync.m16n8k16 (fp16 in, fp32 accum).
//     BM=64 BN=128 BK=32(halfs), 256 threads (8 warps, 2x4), reg prefetch,
//     3 CTAs/SM. Strides 40 halfs (20 words) -> conflict-free frag loads.
// ---------------------------------------------------------------------------
#define BM 64
#define BN 128
#define BK 32
#define ASTH 40   // A smem row stride (halfs); 20 words -> banks 20g+tg distinct
#define BSTH 40   // B smem row stride (halfs)

__device__ __forceinline__ void mma_f16(float c[4], const uint32_t a[4],
                                        uint32_t b0, uint32_t b1) {
    asm volatile(
        "mma.sync.aligned.m16n8k16.row.col.f32.f16.f16.f32 "
        "{%0,%1,%2,%3},{%4,%5,%6,%7},{%8,%9},{%0,%1,%2,%3};"
        : "+f"(c[0]), "+f"(c[1]), "+f"(c[2]), "+f"(c[3])
        : "r"(a[0]), "r"(a[1]), "r"(a[2]), "r"(a[3]), "r"(b0), "r"(b1));
}

__global__ __launch_bounds__(256, 3)
void k4_gemm(float* __restrict__ out) {
    __shared__ __align__(16) __half As[BM * ASTH];   // 5120 B
    __shared__ __align__(16) __half Bs[BN * BSTH];   // 10240 B

    int b   = blockIdx.z;
    int i0  = blockIdx.y * BM;
    int f0  = blockIdx.x * BN;
    int tid = threadIdx.x;
    int wid = tid >> 5, lane = tid & 31;
    int g = lane >> 2, tg = lane & 3;
    int wm = (wid & 1) * 32;    // 2 warp rows
    int wn = (wid >> 1) * 32;   // 4 warp cols

    const uint32_t* As32 = (const uint32_t*)As;
    const uint32_t* Bs32 = (const uint32_t*)Bs;

    float acc[2][4][4];
    #pragma unroll
    for (int t = 0; t < 2; t++)
        #pragma unroll
        for (int u = 0; u < 4; u++)
            #pragma unroll
            for (int q = 0; q < 4; q++) acc[t][u][q] = 0.f;

    // A fill: 64 rows x 32 halfs = 256 uint4; thread t -> row t>>2, 8-half chunk t&3
    int arow = tid >> 2, ac8 = (tid & 3) * 8;
    const __half* aG = g_wh + ((size_t)(b * N1 + i0 + arow)) * N2 + ac8;
    // B fill: 128 rows x 32 halfs = 512 uint4; 2 per thread (rows +64)
    const __half* bG = g_wth + ((size_t)(b * FF + f0 + arow)) * N2 + ac8;

    uint4 ra, rb[2];
    ra    = *(const uint4*)(aG);
    rb[0] = *(const uint4*)(bG);
    rb[1] = *(const uint4*)(bG + (size_t)64 * N2);

    for (int kt = 0; kt < N2 / BK; kt++) {
        // ---- store current tile ----
        *(uint4*)(As + arow * ASTH + ac8) = ra;
        *(uint4*)(Bs + arow * BSTH + ac8)        = rb[0];
        *(uint4*)(Bs + (arow + 64) * BSTH + ac8) = rb[1];
        __syncthreads();

        // ---- prefetch next tile ----
        if (kt + 1 < N2 / BK) {
            int k0 = (kt + 1) * BK;
            ra    = *(const uint4*)(aG + k0);
            rb[0] = *(const uint4*)(bG + k0);
            rb[1] = *(const uint4*)(bG + (size_t)64 * N2 + k0);
        }

        // ---- 2 k-steps of 16 ----
        #pragma unroll
        for (int s = 0; s < 2; s++) {
            int kw = s * 8 + tg;   // word offset within row (k/2)
            uint32_t afr[2][4];
            #pragma unroll
            for (int t = 0; t < 2; t++) {
                int mb = wm + t * 16;
                afr[t][0] = As32[(mb + g)     * (ASTH / 2) + kw];
                afr[t][1] = As32[(mb + g + 8) * (ASTH / 2) + kw];
                afr[t][2] = As32[(mb + g)     * (ASTH / 2) + kw + 4];
                afr[t][3] = As32[(mb + g + 8) * (ASTH / 2) + kw + 4];
            }
            #pragma unroll
            for (int u = 0; u < 4; u++) {
                int n = wn + u * 8 + g;
                uint32_t b0 = Bs32[n * (BSTH / 2) + kw];
                uint32_t b1 = Bs32[n * (BSTH / 2) + kw + 4];
                #pragma unroll
                for (int t = 0; t < 2; t++)
                    mma_f16(acc[t][u], afr[t], b0, b1);
            }
        }
        __syncthreads();
    }

    // ---- epilogue: float2 stores ----
    #pragma unroll
    for (int t = 0; t < 2; t++) {
        int rowg = i0 + wm + t * 16 + g;
        #pragma unroll
        for (int u = 0; u < 4; u++) {
            int col = f0 + wn + u * 8 + 2 * tg;
            float2 v0 = make_float2(acc[t][u][0], acc[t][u][1]);
            float2 v1 = make_float2(acc[t][u][2], acc[t][u][3]);
            *(float2*)(out + ((size_t)(b * N1 + rowg)) * FF + col)     = v0;
            *(float2*)(out + ((size_t)(b * N1 + rowg + 8)) * FF + col) = v1;
        }
    }
}

// ---------------------------------------------------------------------------
extern "C" void kernel_launch(void* const* d_in, const int* in_sizes, int n_in,
                              void* d_out, int out_size) {
    (void)out_size;
    const float *word = nullptr, *adj = nullptr, *W1 = nullptr, *W2 = nullptr, *w3 = nullptr;
    for (int i = 0; i < n_in; i++) {
        int sz = in_sizes[i];
        const float* p = (const float*)d_in[i];
        if      (sz == BB * N1 * N2) adj = p;
        else if (sz == BB * N2 * FF) word = p;
        else if (sz == 2 * FF)       w3 = p;
        else if (sz == FF * FF)      { if (!W1) W1 = p; else W2 = p; }
    }
    float* out = (float*)d_out;

    k1_vec<<<64, 256>>>(W1, W2, w3);
    k2_proj<<<(BB * N2) / 8, 256>>>(word);
    k2t_transpose<<<dim3(N2 / 32, FF / 32, BB), 256>>>(word);
    k3_stats<<<BB * N1, 256>>>(adj);
    k4_gemm<<<dim3(FF / BN, N1 / BM, BB), 256>>>(out);
}

// round 9
// speedup vs baseline: 1.6012x; 1.0247x over previous
#include <cuda_runtime.h>
#include <cuda_fp16.h>
#include <cstdint>

// Problem constants (fixed by the dataset)
#define BB 4
#define N1 2048
#define N2 2048
#define FF 256
#define NEG_ALPHA 0.2f

// Scratch (static __device__ — no allocations allowed)
__device__ float g_v1[FF];
__device__ float g_v2[FF];
__device__ float g_s1[BB * N2];
__device__ float g_t2[BB * N2];
__device__ float g_e1[BB * N2];
__device__ float g_p1[BB * N2];
__device__ __half g_wh[(size_t)BB * N1 * N2];   // attention weights (fp16), 32MB
__device__ __half g_wth[(size_t)BB * FF * N2];  // word transposed (fp16): [b][f][k], 4MB

// ---------------------------------------------------------------------------
// K1: v1 = W1 @ w3[:256], v2 = W2 @ w3[256:]
// ---------------------------------------------------------------------------
__global__ void k1_vec(const float* __restrict__ W1, const float* __restrict__ W2,
                       const float* __restrict__ w3) {
    int gw   = blockIdx.x * 8 + (threadIdx.x >> 5);
    int lane = threadIdx.x & 31;
    int which = gw >> 8;
    int f     = gw & 255;
    const float* W = which ? W2 : W1;
    const float* w = w3 + (which ? FF : 0);
    float s = 0.f;
    #pragma unroll
    for (int k = 0; k < 8; k++)
        s += W[f * FF + lane + 32 * k] * w[lane + 32 * k];
    #pragma unroll
    for (int o = 16; o > 0; o >>= 1)
        s += __shfl_down_sync(0xffffffffu, s, o);
    if (lane == 0) {
        if (which) g_v2[f] = s; else g_v1[f] = s;
    }
}

// ---------------------------------------------------------------------------
// K2: per node j: s1, t2, exp(s1), exp(.2 s1)
// ---------------------------------------------------------------------------
__global__ void k2_proj(const float* __restrict__ word) {
    int row  = blockIdx.x * 8 + (threadIdx.x >> 5);
    int lane = threadIdx.x & 31;
    const float* wr = word + (size_t)row * FF;
    float s = 0.f, t = 0.f;
    #pragma unroll
    for (int k = 0; k < 8; k++) {
        float x = wr[lane + 32 * k];
        s += x * g_v1[lane + 32 * k];
        t += x * g_v2[lane + 32 * k];
    }
    #pragma unroll
    for (int o = 16; o > 0; o >>= 1) {
        s += __shfl_down_sync(0xffffffffu, s, o);
        t += __shfl_down_sync(0xffffffffu, t, o);
    }
    if (lane == 0) {
        g_s1[row] = s;
        g_t2[row] = t;
        g_e1[row] = __expf(s);
        g_p1[row] = __expf(NEG_ALPHA * s);
    }
}

// ---------------------------------------------------------------------------
// K2T: g_wth[b][f][k] = half(word[b][k][f])  (tiled transpose)
// ---------------------------------------------------------------------------
__global__ void k2t_transpose(const float* __restrict__ word) {
    __shared__ float t[32][33];
    int b  = blockIdx.z;
    int k0 = blockIdx.x * 32;
    int f0 = blockIdx.y * 32;
    int r = threadIdx.x >> 5;     // 0..7
    int c = threadIdx.x & 31;
    #pragma unroll
    for (int it = 0; it < 4; it++) {
        int k = k0 + r + 8 * it;
        t[r + 8 * it][c] = word[((size_t)(b * N2 + k)) * FF + f0 + c];
    }
    __syncthreads();
    #pragma unroll
    for (int it = 0; it < 4; it++) {
        int f = f0 + r + 8 * it;
        g_wth[((size_t)(b * FF + f)) * N2 + k0 + c] = __float2half_rn(t[c][r + 8 * it]);
    }
}

// ---------------------------------------------------------------------------
// K3: per output row (b,i): deg, s2, Z, then write softmax weights (fp16).
//     Vectorized: each thread owns 8 CONTIGUOUS columns -> LDG.128/STG.128.
// ---------------------------------------------------------------------------
__global__ void k3_stats(const float* __restrict__ adj) {
    __shared__ float shd[8], shs[8];
    __shared__ float bc[4];
    int row = blockIdx.x;
    int b   = row >> 11;
    int tid = threadIdx.x;
    int base = b << 11;
    int col0 = tid * 8;

    float a[8], tv[8];
    *(float4*)(a)      = *(const float4*)(adj + (size_t)row * N2 + col0);
    *(float4*)(a + 4)  = *(const float4*)(adj + (size_t)row * N2 + col0 + 4);
    *(float4*)(tv)     = *(const float4*)(g_t2 + base + col0);
    *(float4*)(tv + 4) = *(const float4*)(g_t2 + base + col0 + 4);

    float deg = 0.f, sr = 0.f;
    #pragma unroll
    for (int k = 0; k < 8; k++) { deg += a[k]; sr += a[k] * tv[k]; }
    #pragma unroll
    for (int o = 16; o > 0; o >>= 1) {
        deg += __shfl_down_sync(0xffffffffu, deg, o);
        sr  += __shfl_down_sync(0xffffffffu, sr,  o);
    }
    int w = tid >> 5, ln = tid & 31;
    if (ln == 0) { shd[w] = deg; shs[w] = sr; }
    __syncthreads();
    if (tid == 0) {
        float D = 0.f, S = 0.f;
        #pragma unroll
        for (int q = 0; q < 8; q++) { D += shd[q]; S += shs[q]; }
        float s2 = S / fmaxf(D, 1.0f);
        bc[0] = s2;
        bc[1] = __expf(s2);
        bc[2] = __expf(NEG_ALPHA * s2);
        bc[3] = D;
    }
    __syncthreads();
    float s2 = bc[0], E2 = bc[1], P2 = bc[2], D = bc[3];

    float s1v[8], e1v[8], p1v[8], e[8];
    *(float4*)(s1v)     = *(const float4*)(g_s1 + base + col0);
    *(float4*)(s1v + 4) = *(const float4*)(g_s1 + base + col0 + 4);
    *(float4*)(e1v)     = *(const float4*)(g_e1 + base + col0);
    *(float4*)(e1v + 4) = *(const float4*)(g_e1 + base + col0 + 4);
    *(float4*)(p1v)     = *(const float4*)(g_p1 + base + col0);
    *(float4*)(p1v + 4) = *(const float4*)(g_p1 + base + col0 + 4);

    float z = 0.f;
    #pragma unroll
    for (int k = 0; k < 8; k++) {
        float pre   = s2 + s1v[k];
        float inner = (pre >= 0.f) ? E2 * e1v[k] : P2 * p1v[k];
        e[k] = __expf(inner);
        z   += a[k] * e[k];
    }
    #pragma unroll
    for (int o = 16; o > 0; o >>= 1) z += __shfl_down_sync(0xffffffffu, z, o);
    if (ln == 0) shd[w] = z;
    __syncthreads();
    if (tid == 0) {
        float Z = 0.f;
        #pragma unroll
        for (int q = 0; q < 8; q++) Z += shd[q];
        bc[0] = (D > 0.f) ? (1.0f / Z) : -1.0f;
    }
    __syncthreads();
    float invZ = bc[0];

    __half2 h[4];
    #pragma unroll
    for (int q = 0; q < 4; q++) {
        float w0 = (invZ < 0.f) ? (1.0f / 2048.0f)
                                : (a[2 * q]     > 0.f ? e[2 * q]     * invZ : 0.f);
        float w1 = (invZ < 0.f) ? (1.0f / 2048.0f)
                                : (a[2 * q + 1] > 0.f ? e[2 * q + 1] * invZ : 0.f);
        h[q] = __floats2half2_rn(w0, w1);
    }
    *(uint4*)(g_wh + (size_t)row * N2 + col0) = *(uint4*)h;
}

// ---------------------------------------------------------------------------
// K4: edge = W @ word via HMMA mma.sync.m16n8k16 (fp16 in, fp32 accum).
//     BM=64 BN=128 BK=32(halfs), 256 threads (8 warps, 2x4),
//     double-buffered smem (one __syncthreads per k-tile), 3 CTAs/SM.
// ---------------------------------------------------------------------------
#define BM 64
#define BN 128
#define BK 32
#define ASTH 40   // A smem row stride (halfs); 20 words -> banks 20g+tg distinct
#define BSTH 40   // B smem row stride (halfs)
#define NKI (N2 / BK)

__device__ __forceinline__ void mma_f16(float c[4], const uint32_t a[4],
                                        uint32_t b0, uint32_t b1) {
    asm volatile(
        "mma.sync.aligned.m16n8k16.row.col.f32.f16.f16.f32 "
        "{%0,%1,%2,%3},{%4,%5,%6,%7},{%8,%9},{%0,%1,%2,%3};"
        : "+f"(c[0]), "+f"(c[1]), "+f"(c[2]), "+f"(c[3])
        : "r"(a[0]), "r"(a[1]), "r"(a[2]), "r"(a[3]), "r"(b0), "r"(b1));
}

__global__ __launch_bounds__(256, 3)
void k4_gemm(float* __restrict__ out) {
    __shared__ __align__(16) __half As[2][BM * ASTH];   // 2 x 5120 B
    __shared__ __align__(16) __half Bs[2][BN * BSTH];   // 2 x 10240 B

    int b   = blockIdx.z;
    int i0  = blockIdx.y * BM;
    int f0  = blockIdx.x * BN;
    int tid = threadIdx.x;
    int wid = tid >> 5, lane = tid & 31;
    int g = lane >> 2, tg = lane & 3;
    int wm = (wid & 1) * 32;    // 2 warp rows
    int wn = (wid >> 1) * 32;   // 4 warp cols

    float acc[2][4][4];
    #pragma unroll
    for (int t = 0; t < 2; t++)
        #pragma unroll
        for (int u = 0; u < 4; u++)
            #pragma unroll
            for (int q = 0; q < 4; q++) acc[t][u][q] = 0.f;

    // fill mapping: thread t -> row t>>2, 8-half chunk (t&3)*8
    int arow = tid >> 2, ac8 = (tid & 3) * 8;
    const __half* aG = g_wh + ((size_t)(b * N1 + i0 + arow)) * N2 + ac8;
    const __half* bG = g_wth + ((size_t)(b * FF + f0 + arow)) * N2 + ac8;

    uint4 ra, rb0, rb1;
    ra  = *(const uint4*)(aG);
    rb0 = *(const uint4*)(bG);
    rb1 = *(const uint4*)(bG + (size_t)64 * N2);
    *(uint4*)(As[0] + arow * ASTH + ac8)        = ra;
    *(uint4*)(Bs[0] + arow * BSTH + ac8)        = rb0;
    *(uint4*)(Bs[0] + (arow + 64) * BSTH + ac8) = rb1;
    __syncthreads();

    for (int kt = 0; kt < NKI; kt++) {
        int cur = kt & 1;

        // ---- prefetch next tile (LDG issued before mma consumes smem) ----
        if (kt + 1 < NKI) {
            int k0 = (kt + 1) * BK;
            ra  = *(const uint4*)(aG + k0);
            rb0 = *(const uint4*)(bG + k0);
            rb1 = *(const uint4*)(bG + (size_t)64 * N2 + k0);
        }

        const uint32_t* As32 = (const uint32_t*)As[cur];
        const uint32_t* Bs32 = (const uint32_t*)Bs[cur];

        // ---- 2 k-steps of 16 ----
        #pragma unroll
        for (int s = 0; s < 2; s++) {
            int kw = s * 8 + tg;   // word offset within row (k/2)
            uint32_t afr[2][4];
            #pragma unroll
            for (int t = 0; t < 2; t++) {
                int mb = wm + t * 16;
                afr[t][0] = As32[(mb + g)     * (ASTH / 2) + kw];
                afr[t][1] = As32[(mb + g + 8) * (ASTH / 2) + kw];
                afr[t][2] = As32[(mb + g)     * (ASTH / 2) + kw + 4];
                afr[t][3] = As32[(mb + g + 8) * (ASTH / 2) + kw + 4];
            }
            #pragma unroll
            for (int u = 0; u < 4; u++) {
                int n = wn + u * 8 + g;
                uint32_t b0 = Bs32[n * (BSTH / 2) + kw];
                uint32_t b1 = Bs32[n * (BSTH / 2) + kw + 4];
                #pragma unroll
                for (int t = 0; t < 2; t++)
                    mma_f16(acc[t][u], afr[t], b0, b1);
            }
        }

        // ---- store prefetched tile into the other buffer ----
        if (kt + 1 < NKI) {
            int nxt = (kt + 1) & 1;
            *(uint4*)(As[nxt] + arow * ASTH + ac8)        = ra;
            *(uint4*)(Bs[nxt] + arow * BSTH + ac8)        = rb0;
            *(uint4*)(Bs[nxt] + (arow + 64) * BSTH + ac8) = rb1;
        }
        __syncthreads();
    }

    // ---- epilogue: float2 stores ----
    #pragma unroll
    for (int t = 0; t < 2; t++) {
        int rowg = i0 + wm + t * 16 + g;
        #pragma unroll
        for (int u = 0; u < 4; u++) {
            int col = f0 + wn + u * 8 + 2 * tg;
            float2 v0 = make_float2(acc[t][u][0], acc[t][u][1]);
            float2 v1 = make_float2(acc[t][u][2], acc[t][u][3]);
            *(float2*)(out + ((size_t)(b * N1 + rowg)) * FF + col)     = v0;
            *(float2*)(out + ((size_t)(b * N1 + rowg + 8)) * FF + col) = v1;
        }
    }
}

// ---------------------------------------------------------------------------
extern "C" void kernel_launch(void* const* d_in, const int* in_sizes, int n_in,
                              void* d_out, int out_size) {
    (void)out_size;
    const float *word = nullptr, *adj = nullptr, *W1 = nullptr, *W2 = nullptr, *w3 = nullptr;
    for (int i = 0; i < n_in; i++) {
        int sz = in_sizes[i];
        const float* p = (const float*)d_in[i];
        if      (sz == BB * N1 * N2) adj = p;
        else if (sz == BB * N2 * FF) word = p;
        else if (sz == 2 * FF)       w3 = p;
        else if (sz == FF * FF)      { if (!W1) W1 = p; else W2 = p; }
    }
    float* out = (float*)d_out;

    k1_vec<<<64, 256>>>(W1, W2, w3);
    k2_proj<<<(BB * N2) / 8, 256>>>(word);
    k2t_transpose<<<dim3(N2 / 32, FF / 32, BB), 256>>>(word);
    k3_stats<<<BB * N1, 256>>>(adj);
    k4_gemm<<<dim3(FF / BN, N1 / BM, BB), 256>>>(out);
}